// round 15
// baseline (speedup 1.0000x reference)
#include <cuda_runtime.h>
#include <math.h>
#include <stdint.h>

#define HID     100
#define NPATH   4864
#define NPAD    6800          // k-padded coeff table: per pair (v*17+u)*KP+k
#define NSEG    101
#define NCYT    376           // k-padded CY table
#define ABCHUNK 8
#define NPTS    8192
#define PCTAS   592           // 148 SMs * 4 resident CTAs

// ---------------- static device scratch (zero-initialized -> pads stay 0) ----------------
__device__ float g_T[HID];
__device__ float g_CG[1225];
__device__ int   g_slotdesc[259];
__device__ __align__(16) float g_A[NSEG*NPAD];
__device__ __align__(16) float g_B[NSEG*NPAD];

__constant__ int d_NLF[9]   = {1,1,1, 1,3,3, 1,3,5};
__constant__ int d_KP[9]    = {1,1,1, 1,4,4, 1,4,8};
__constant__ int d_TBASE[9] = {0,1,2, 3,4,7, 10,11,14};
__constant__ int d_CYTB[9]  = {0,1,4, 9,12,48, 108,116,176};
__constant__ int d_CGOFF[19]= {0,1,10,35,44,53,80,125,170,245,350,375,420,495,600,625,700,825,1000};
__constant__ int d_TLO[19]  = {0,0,0,1,1,1,1,1,1,1,2,2,2,2,2,2,2,2,2};
__constant__ int d_TLI[19]  = {0,1,2,0,1,1,1,2,2,2,0,1,1,1,2,2,2,2,2};
__constant__ int d_TLF[19]  = {0,1,2,1,0,1,2,1,2,3,2,1,2,3,0,1,2,3,4};

// original path index -> padded layout index
__device__ __forceinline__ int permute_pad(int p){
    int base, nlf, kp, pbn;
    if      (p < 256)  { base=0;    nlf=1; kp=1; pbn=0;    }
    else if (p < 512)  { base=256;  nlf=1; kp=1; pbn=272;  }
    else if (p < 768)  { base=512;  nlf=1; kp=1; pbn=544;  }
    else if (p < 1024) { base=768;  nlf=1; kp=1; pbn=816;  }
    else if (p < 1792) { base=1024; nlf=3; kp=4; pbn=1088; }
    else if (p < 2560) { base=1792; nlf=3; kp=4; pbn=2176; }
    else if (p < 2816) { base=2560; nlf=1; kp=1; pbn=3264; }
    else if (p < 3584) { base=2816; nlf=3; kp=4; pbn=3536; }
    else               { base=3584; nlf=5; kp=8; pbn=4624; }
    int local = p - base;
    int u   = local / (16*nlf);
    int rem = local - u*16*nlf;
    int v = rem / nlf, k = rem - v*nlf;
    return pbn + (v*17 + u)*kp + k;
}

// ---------------- CG helpers (fp32, reciprocal factorial table) ----------------
__device__ float cgvalf(int j1,int j2,int j3,int m1,int m2,
                        const float* __restrict__ F, const float* __restrict__ Fi,
                        float pref0){
    int m3 = m1 + m2;
    if (abs(m3) > j3) return 0.f;
    float pref = pref0 * sqrtf(F[j3+m3]*F[j3-m3]*F[j1-m1]*F[j1+m1]*F[j2-m2]*F[j2+m2]);
    int klo = max(0, max(j2-j3-m1, j1+m2-j3));
    int khi = min(j1+j2-j3, min(j1-m1, j2+m2));
    float s = 0.f;
    for (int k = klo; k <= khi; k++){
        float d = Fi[k]*Fi[j1+j2-j3-k]*Fi[j1-m1-k]*Fi[j2+m2-k]*Fi[j3-j2+m1+k]*Fi[j3-j1-m2+k];
        s += (k & 1) ? -d : d;
    }
    return pref * s;
}
__device__ __forceinline__ float w3j_entryf(int j1,int j2,int j3,int mi,int ni,int ki,
                                            const float* __restrict__ F, const float* __restrict__ Fi,
                                            float pref0, float inv2j3){
    int m1 = mi - j1, m2 = ni - j2, m3 = ki - j3;
    if (m1 + m2 + m3 != 0) return 0.f;
    float cg = cgvalf(j1, j2, j3, m1, m2, F, Fi, pref0);
    float sgn = ((j1 - j2 + m3) & 1) ? -1.f : 1.f;
    return sgn * cg * inv2j3;
}
__device__ __forceinline__ void qvalcf(int l, int i, int j, float& re, float& im){
    re = 0.f; im = 0.f;
    const float s2 = 0.70710678118654752f;
    int m = i - l;
    if (m == 0){ if (j == l) re = 1.f; return; }
    if (m > 0){
        if (j == l+m)      re = (m & 1) ? -s2 : s2;
        else if (j == l-m) re = s2;
    } else {
        int mm = -m;
        if (j == l-mm)      im = s2;
        else if (j == l+mm) im = (mm & 1) ? s2 : -s2;
    }
}
__device__ __forceinline__ int qcols(int l, int row, int* s){
    if (row == l){ s[0] = l; return 1; }
    s[0] = row; s[1] = 2*l - row; return 2;
}

// ============== ONE fused init kernel ==============
// blocks 0..18  : CG tensors
// block  19     : threshold sort (g_T) + slot descriptors
// blocks 20..266: A/B table chunks (local sort recomputed per block -> no dependency)
__global__ void k_init_all(const float* __restrict__ W1, const float* __restrict__ b1,
                           const float* __restrict__ W2){
    int bid = blockIdx.x;
    int t = threadIdx.x;

    if (bid < 19){
        int tens = bid;
        int lo = d_TLO[tens], li = d_TLI[tens], lf = d_TLF[tens];
        int da = 2*lo+1, db = 2*li+1, dc = 2*lf+1;
        int n = da*db*dc;
        __shared__ float sre[225], sim2[225];
        __shared__ float sF[12], sFi[12];
        __shared__ float s_pref0, s_inv2j3, s_nr, s_ni;
        if (t == 0){
            float f = 1.f;
            sF[0] = 1.f; sFi[0] = 1.f;
            for (int i = 1; i < 12; i++){ f *= (float)i; sF[i] = f; sFi[i] = 1.f/f; }
            s_pref0 = sqrtf((float)(2*lf+1) * sF[lo+li-lf] * sF[lo-li+lf] * sF[-lo+li+lf] * sFi[lo+li+lf+1]);
            s_inv2j3 = rsqrtf((float)(2*lf+1));
        }
        __syncthreads();
        const float* F = sF; const float* Fi = sFi;
        for (int e = t; e < n; e += blockDim.x){
            int cc = e % dc; int ab = e / dc; int b = ab % db; int a = ab / db;
            int mset[2], nset[2], kset[2];
            int nm = qcols(lo, a, mset);
            int nn = qcols(li, b, nset);
            int nk = qcols(lf, cc, kset);
            float re = 0.f, imv = 0.f;
            for (int i1 = 0; i1 < nm; i1++){
                float q1r, q1i; qvalcf(lo, a, mset[i1], q1r, q1i);
                for (int i2 = 0; i2 < nn; i2++){
                    float q2r, q2i; qvalcf(li, b, nset[i2], q2r, q2i);
                    float q12r = q1r*q2r - q1i*q2i;
                    float q12i = q1r*q2i + q1i*q2r;
                    for (int i3 = 0; i3 < nk; i3++){
                        float q3r, q3i; qvalcf(lf, cc, kset[i3], q3r, q3i);
                        float w = w3j_entryf(lo, li, lf, mset[i1], nset[i2], kset[i3], F, Fi, s_pref0, s_inv2j3);
                        if (w != 0.f){
                            re  += (q12r*q3r - q12i*q3i) * w;
                            imv += (q12r*q3i + q12i*q3r) * w;
                        }
                    }
                }
            }
            sre[e] = re; sim2[e] = imv;
        }
        __syncthreads();
        if (t == 0){
            float nr = 0.f, ni = 0.f;
            for (int e = 0; e < n; e++){ nr += sre[e]*sre[e]; ni += sim2[e]*sim2[e]; }
            s_nr = nr; s_ni = ni;
        }
        __syncthreads();
        bool use_re = (s_nr >= s_ni);
        float inv = rsqrtf(use_re ? s_nr : s_ni);
        int base = d_CGOFF[tens];
        for (int e = t; e < n; e += blockDim.x)
            g_CG[base + e] = (use_re ? sre[e] : sim2[e]) * inv;
        return;
    }

    if (bid == 19){
        __shared__ float th[HID];
        if (t < HID){
            float w = W1[t];
            th[t] = (w != 0.0f) ? (-b1[t] / w) : -1e30f;
        }
        __syncthreads();
        if (t < HID){
            float mine = th[t];
            int rank = 0;
            for (int i = 0; i < HID; i++){
                float o = th[i];
                rank += (o < mine) || (o == mine && i < t);
            }
            g_T[rank] = mine;
        }
        if (t == 0){
            int s = 0;
            for (int pair = 0; pair < 9; pair++){
                int lo = pair/3, li = pair%3;
                int da = 2*lo+1, db = 2*li+1;
                int nlf = d_NLF[pair], kp = d_KP[pair];
                int lfmin = (lo > li) ? lo - li : li - lo;
                for (int a = 0; a < da; a++)
                    for (int k = 0; k < nlf; k++)
                        for (int b = 0; b < db; b++){
                            int lf = lfmin + k;
                            int cgbase = d_CGOFF[d_TBASE[pair]+k] + (a*db + b)*(2*lf+1);
                            int tgt = d_CYTB[pair] + (b*da + a)*kp + k;
                            g_slotdesc[s++] = cgbase | (lf<<11) | (lo<<14) | (li<<16) | (tgt<<18);
                        }
            }
        }
        return;
    }

    // ---- A/B table blocks (local sort: no dependency on block 19) ----
    {
        int pb = bid - 20;
        int px = pb % 19, py = pb / 19;
        int s0 = py * ABCHUNK;

        __shared__ float sW1[HID], sb1[HID], sth[HID];
        __shared__ int   ssid[HID], srnk[HID];
        if (t < HID){
            float w = W1[t], bb = b1[t];
            sW1[t] = w; sb1[t] = bb;
            sth[t] = (w != 0.0f) ? (-bb / w) : -1e30f;
        }
        __syncthreads();
        if (t < HID){
            float mine = sth[t];
            int rank = 0;
            for (int i = 0; i < HID; i++){
                float o = sth[i];
                rank += (o < mine) || (o == mine && i < t);
            }
            srnk[t] = rank;
            ssid[rank] = t;
        }
        __syncthreads();

        int p = px*256 + t;             // 19*256 == NPATH exactly
        int pn = permute_pad(p);

        float A = 0.f, Bv = 0.f;
        for (int tt = 0; tt < HID; tt++){
            float w = sW1[tt], bb = sb1[tt];
            int rk = srnk[tt];
            bool act = (w > 0.0f) ? (rk < s0) : ((w < 0.0f) ? (rk >= s0) : (bb > 0.0f));
            if (act){
                float w2 = W2[tt*NPATH + p];
                A  = fmaf(w,  w2, A);
                Bv = fmaf(bb, w2, Bv);
            }
        }
        g_A[s0*NPAD + pn] = A;
        g_B[s0*NPAD + pn] = Bv;
        #pragma unroll
        for (int d = 1; d < ABCHUNK; d++){
            int s = s0 + d;
            if (s >= NSEG) break;
            int u  = ssid[s-1];
            float w = sW1[u], bb = sb1[u];
            float w2 = W2[u*NPATH + p];
            float sg = (w > 0.0f) ? 1.0f : ((w < 0.0f) ? -1.0f : 0.0f);
            A  = fmaf(sg*w,  w2, A);
            Bv = fmaf(sg*bb, w2, Bv);
            g_A[s*NPAD + pn] = A;
            g_B[s*NPAD + pn] = Bv;
        }
    }
}

// ============== main kernel (persistent) ==============
template<int DA,int NLF,int KP>
__device__ __forceinline__ void pass(const float* __restrict__ cyb,  // sCYT + CYB + j*DA*KP
                                     const float* __restrict__ cfb,  // sC + PB + v*17*KP
                                     float* __restrict__ outp,       // out + rowbase*144 + col
                                     int u0, int NU){
    float cy[DA*NLF];
    #pragma unroll
    for (int i = 0; i < DA; i++){
        if (KP == 4 && NLF == 3){
            float4 v4 = *(const float4*)(cyb + i*KP);
            cy[i*NLF+0]=v4.x; cy[i*NLF+1]=v4.y; cy[i*NLF+2]=v4.z;
        } else if (KP == 8 && NLF == 5){
            float4 v4 = *(const float4*)(cyb + i*KP);
            cy[i*NLF+0]=v4.x; cy[i*NLF+1]=v4.y; cy[i*NLF+2]=v4.z; cy[i*NLF+3]=v4.w;
            cy[i*NLF+4]=cyb[i*KP+4];
        } else {
            #pragma unroll
            for (int k = 0; k < NLF; k++) cy[i*NLF+k] = cyb[i*KP+k];
        }
    }
    for (int ug = 0; ug < NU; ug++){
        const float* cfp = cfb + (u0+ug)*KP;
        float cf[NLF];
        if (KP == 4 && NLF == 3){
            float4 v4 = *(const float4*)cfp;
            cf[0]=v4.x; cf[1]=v4.y; cf[2]=v4.z;
        } else if (KP == 8 && NLF == 5){
            float4 v4 = *(const float4*)cfp;
            cf[0]=v4.x; cf[1]=v4.y; cf[2]=v4.z; cf[3]=v4.w; cf[4]=cfp[4];
        } else {
            #pragma unroll
            for (int k = 0; k < NLF; k++) cf[k] = cfp[k];
        }
        #pragma unroll
        for (int i = 0; i < DA; i++){
            float val = 0.f;
            #pragma unroll
            for (int k = 0; k < NLF; k++) val = fmaf(cy[i*NLF+k], cf[k], val);
            __stcs(outp + (ug*DA + i)*144, val);
        }
    }
}

template<int DA,int NLF1,int KP1,int NLF2,int KP2>
__device__ __forceinline__ void warp_work(const float* __restrict__ sC,
                                          const float* __restrict__ sCYT,
                                          float* __restrict__ outz,
                                          int l, int u0, int NU, int loBase,
                                          int PB0, int PB1, int PB2,
                                          int CY0, int CY1, int CY2){
    int c16 = l & 15, h = l >> 4;
    int NU0 = (NU + 1) >> 1;
    int u0h = h ? (u0 + NU0) : u0;
    int NUh = h ? (NU - NU0) : NU0;
    float* outw = outz + (loBase + u0 *DA)*144;
    float* outh = outz + (loBase + u0h*DA)*144;

    pass<DA,1,1>(sCYT + CY0, sC + PB0 + c16*17, outh + c16, u0h, NUh);
    { int cc = l; int v = cc/3, j = cc - 3*v;
      pass<DA,NLF1,KP1>(sCYT + CY1 + j*DA*KP1, sC + PB1 + v*17*KP1, outw + 16 + cc, u0, NU); }
    { int cc = 32 + c16; int v = cc/3, j = cc - 3*v;
      pass<DA,NLF1,KP1>(sCYT + CY1 + j*DA*KP1, sC + PB1 + v*17*KP1, outh + 16 + cc, u0h, NUh); }
    { int cc = l; int v = cc/5, j = cc - 5*v;
      pass<DA,NLF2,KP2>(sCYT + CY2 + j*DA*KP2, sC + PB2 + v*17*KP2, outw + 64 + cc, u0, NU); }
    { int cc = 32 + l; int v = cc/5, j = cc - 5*v;
      pass<DA,NLF2,KP2>(sCYT + CY2 + j*DA*KP2, sC + PB2 + v*17*KP2, outw + 64 + cc, u0, NU); }
    { int cc = 64 + c16; int v = cc/5, j = cc - 5*v;
      pass<DA,NLF2,KP2>(sCYT + CY2 + j*DA*KP2, sC + PB2 + v*17*KP2, outh + 64 + cc, u0h, NUh); }
}

extern __shared__ float smem[];

__global__ __launch_bounds__(288, 4)
void k_main(const float* __restrict__ r, float* __restrict__ out){
    float* sC   = smem;             // NPAD = 6800
    float* sCYT = sC + NPAD;        // 376
    float* sY   = sCYT + NCYT;      // 32

    int tid = threadIdx.x;
    int w   = tid >> 5, l = tid & 31;

    // zero CY pad region once (pads never rewritten)
    if (tid < 188){ sCYT[tid] = 0.f; sCYT[tid + 188] = 0.f; }

    // per-warp constants for the compute phase
    int u0, NU, loBase;
    if (w == 0){ u0 = 0; NU = 16; loBase = 0; }
    else if (w < 4){ u0 = (w == 1) ? 0 : ((w == 2) ? 6 : 11); NU = (w == 1) ? 6 : 5; loBase = 16; }
    else { int wi = w - 4; u0 = (wi == 0) ? 0 : (4 + 3*(wi-1)); NU = (wi == 0) ? 4 : 3; loBase = 64; }

    float myT = (tid < HID) ? g_T[tid] : 3.4e38f;

    for (int z = blockIdx.x; z < NPTS; z += PCTAS){
        float x = __ldg(&r[3*z+0]), y = __ldg(&r[3*z+1]), zz = __ldg(&r[3*z+2]);
        float rad = sqrtf(x*x + y*y + zz*zz);
        bool  iszero = (rad == 0.0f);
        float inv = 1.0f / fmaxf(rad, 1e-12f);
        float ux = x*inv, uy = y*inv, uz = zz*inv;

        if (tid == 0){
            float X = ux, Y = uy, Z = uz;
            float X2 = X*X, Y2 = Y*Y, Z2 = Z*Z;
            sY[0]  = 0.28209479177387814f;
            sY[1]  = 0.4886025119029199f * Y;
            sY[2]  = 0.4886025119029199f * Z;
            sY[3]  = 0.4886025119029199f * X;
            sY[4]  = 1.0925484305920792f * X*Y;
            sY[5]  = 1.0925484305920792f * Y*Z;
            sY[6]  = 0.31539156525252005f * (3.f*Z2 - 1.f);
            sY[7]  = 1.0925484305920792f * X*Z;
            sY[8]  = 0.5462742152960396f * (X2 - Y2);
            sY[9]  = 0.5900435899266435f * Y*(3.f*X2 - Y2);
            sY[10] = 2.890611442640554f  * X*Y*Z;
            sY[11] = 0.4570457994644658f * Y*(5.f*Z2 - 1.f);
            sY[12] = 0.3731763325901154f * Z*(5.f*Z2 - 3.f);
            sY[13] = 0.4570457994644658f * X*(5.f*Z2 - 1.f);
            sY[14] = 1.445305721320277f  * (X2 - Y2)*Z;
            sY[15] = 0.5900435899266435f * X*(X2 - 3.f*Y2);
            sY[16] = 2.5033429417967046f * X*Y*(X2 - Y2);
            sY[17] = 1.7701307697799304f * Y*(3.f*X2 - Y2)*Z;
            sY[18] = 0.9461746957575601f * X*Y*(7.f*Z2 - 1.f);
            sY[19] = 0.6690465435572892f * Y*Z*(7.f*Z2 - 3.f);
            sY[20] = 0.10578554691520431f * (35.f*Z2*Z2 - 30.f*Z2 + 3.f);
            sY[21] = 0.6690465435572892f * X*Z*(7.f*Z2 - 3.f);
            sY[22] = 0.47308734787878004f * (X2 - Y2)*(7.f*Z2 - 1.f);
            sY[23] = 1.7701307697799304f * X*(X2 - 3.f*Y2)*Z;
            sY[24] = 0.6258357354491761f * (X2*X2 - 6.f*X2*Y2 + Y2*Y2);
        }

        // barrier A: all warps done with previous z's passes; sY visible after
        int seg = __syncthreads_count(myT < rad);

        // coeff fill (padded layout), float4: 6800/4 = 1700
        {
            const float4* A4 = (const float4*)(g_A + (size_t)seg * NPAD);
            const float4* B4 = (const float4*)(g_B + (size_t)seg * NPAD);
            float4* sC4 = (float4*)sC;
            #pragma unroll
            for (int it = 0; it < 6; it++){
                int idx = it*288 + tid;
                if (idx < NPAD/4){
                    float4 a = __ldg(&A4[idx]);
                    float4 b = __ldg(&B4[idx]);
                    sC4[idx] = make_float4(fmaf(rad,a.x,b.x), fmaf(rad,a.y,b.y),
                                           fmaf(rad,a.z,b.z), fmaf(rad,a.w,b.w));
                }
            }
        }

        // CY fill into padded CYT
        if (tid < 259){
            int desc = g_slotdesc[tid];
            int cgbase = desc & 0x7FF;
            int lf  = (desc >> 11) & 7;
            int lo  = (desc >> 14) & 3;
            int li  = (desc >> 16) & 3;
            int tgt = desc >> 18;
            int yoff = lf*lf, dc = 2*lf + 1;
            float v = 0.f;
            for (int m = 0; m < dc; m++)
                v = fmaf(g_CG[cgbase + m], sY[yoff + m], v);
            float lm = sqrtf((float)(2*li+1) * 12.566370614359172f);
            float num = (lo == 0) ? 48.f : ((lo == 1) ? 112.f : 144.f);
            float nrm = iszero ? (lm * 0.25f) : (lm * rsqrtf(num));
            sCYT[tgt] = v * nrm;
        }
        __syncthreads();   // barrier B: sC + sCYT ready

        float* outz = out + (size_t)z * 20736;
        if (w == 0){
            warp_work<1,1,1,1,1>(sC, sCYT, outz, l, u0, NU, loBase,
                                 0, 272, 544, 0, 1, 4);
        } else if (w < 4){
            warp_work<3,3,4,3,4>(sC, sCYT, outz, l, u0, NU, loBase,
                                 816, 1088, 2176, 9, 12, 48);
        } else {
            warp_work<5,3,4,5,8>(sC, sCYT, outz, l, u0, NU, loBase,
                                 3264, 3536, 4624, 108, 116, 176);
        }
    }
}

extern "C" void kernel_launch(void* const* d_in, const int* in_sizes, int n_in,
                              void* d_out, int out_size){
    const float* r  = (const float*)d_in[0];
    const float* W1 = (const float*)d_in[1];
    const float* b1 = (const float*)d_in[2];
    const float* W2 = (const float*)d_in[3];
    float* out = (float*)d_out;

    static bool attr_set = false;
    int smem_bytes = (NPAD + NCYT + 32) * 4;
    if (!attr_set){
        cudaFuncSetAttribute(k_main, cudaFuncAttributeMaxDynamicSharedMemorySize, smem_bytes);
        attr_set = true;
    }

    k_init_all<<<20 + 19*((NSEG + ABCHUNK - 1)/ABCHUNK), 256>>>(W1, b1, W2);
    k_main<<<PCTAS, 288, smem_bytes>>>(r, out);
}

// round 16
// speedup vs baseline: 1.1186x; 1.1186x over previous
#include <cuda_runtime.h>
#include <math.h>
#include <stdint.h>

#define HID     100
#define NPATH   4864
#define NPAD    6800          // k-padded coeff table: per pair (v*17+u)*KP+k
#define NSEG    101
#define NCYT    376           // k-padded CY table
#define ABCHUNK 8
#define NPTS    8192

// ---------------- static device scratch (zero-initialized -> pads stay 0) ----------------
__device__ float g_T[HID];
__device__ float g_CG[1225];
__device__ int   g_slotdesc[259];
__device__ __align__(16) float g_A[NSEG*NPAD];
__device__ __align__(16) float g_B[NSEG*NPAD];

__constant__ int d_NLF[9]   = {1,1,1, 1,3,3, 1,3,5};
__constant__ int d_KP[9]    = {1,1,1, 1,4,4, 1,4,8};
__constant__ int d_TBASE[9] = {0,1,2, 3,4,7, 10,11,14};
__constant__ int d_CYTB[9]  = {0,1,4, 9,12,48, 108,116,176};
__constant__ int d_CGOFF[19]= {0,1,10,35,44,53,80,125,170,245,350,375,420,495,600,625,700,825,1000};
__constant__ int d_TLO[19]  = {0,0,0,1,1,1,1,1,1,1,2,2,2,2,2,2,2,2,2};
__constant__ int d_TLI[19]  = {0,1,2,0,1,1,1,2,2,2,0,1,1,1,2,2,2,2,2};
__constant__ int d_TLF[19]  = {0,1,2,1,0,1,2,1,2,3,2,1,2,3,0,1,2,3,4};

// original path index -> padded layout index
__device__ __forceinline__ int permute_pad(int p){
    int base, nlf, kp, pbn;
    if      (p < 256)  { base=0;    nlf=1; kp=1; pbn=0;    }
    else if (p < 512)  { base=256;  nlf=1; kp=1; pbn=272;  }
    else if (p < 768)  { base=512;  nlf=1; kp=1; pbn=544;  }
    else if (p < 1024) { base=768;  nlf=1; kp=1; pbn=816;  }
    else if (p < 1792) { base=1024; nlf=3; kp=4; pbn=1088; }
    else if (p < 2560) { base=1792; nlf=3; kp=4; pbn=2176; }
    else if (p < 2816) { base=2560; nlf=1; kp=1; pbn=3264; }
    else if (p < 3584) { base=2816; nlf=3; kp=4; pbn=3536; }
    else               { base=3584; nlf=5; kp=8; pbn=4624; }
    int local = p - base;
    int u   = local / (16*nlf);
    int rem = local - u*16*nlf;
    int v = rem / nlf, k = rem - v*nlf;
    return pbn + (v*17 + u)*kp + k;
}

// ---------------- CG helpers (fp32, reciprocal factorial table) ----------------
__device__ float cgvalf(int j1,int j2,int j3,int m1,int m2,
                        const float* __restrict__ F, const float* __restrict__ Fi,
                        float pref0){
    int m3 = m1 + m2;
    if (abs(m3) > j3) return 0.f;
    float pref = pref0 * sqrtf(F[j3+m3]*F[j3-m3]*F[j1-m1]*F[j1+m1]*F[j2-m2]*F[j2+m2]);
    int klo = max(0, max(j2-j3-m1, j1+m2-j3));
    int khi = min(j1+j2-j3, min(j1-m1, j2+m2));
    float s = 0.f;
    for (int k = klo; k <= khi; k++){
        float d = Fi[k]*Fi[j1+j2-j3-k]*Fi[j1-m1-k]*Fi[j2+m2-k]*Fi[j3-j2+m1+k]*Fi[j3-j1-m2+k];
        s += (k & 1) ? -d : d;
    }
    return pref * s;
}
__device__ __forceinline__ float w3j_entryf(int j1,int j2,int j3,int mi,int ni,int ki,
                                            const float* __restrict__ F, const float* __restrict__ Fi,
                                            float pref0, float inv2j3){
    int m1 = mi - j1, m2 = ni - j2, m3 = ki - j3;
    if (m1 + m2 + m3 != 0) return 0.f;
    float cg = cgvalf(j1, j2, j3, m1, m2, F, Fi, pref0);
    float sgn = ((j1 - j2 + m3) & 1) ? -1.f : 1.f;
    return sgn * cg * inv2j3;
}
__device__ __forceinline__ void qvalcf(int l, int i, int j, float& re, float& im){
    re = 0.f; im = 0.f;
    const float s2 = 0.70710678118654752f;
    int m = i - l;
    if (m == 0){ if (j == l) re = 1.f; return; }
    if (m > 0){
        if (j == l+m)      re = (m & 1) ? -s2 : s2;
        else if (j == l-m) re = s2;
    } else {
        int mm = -m;
        if (j == l-mm)      im = s2;
        else if (j == l+mm) im = (mm & 1) ? s2 : -s2;
    }
}
__device__ __forceinline__ int qcols(int l, int row, int* s){
    if (row == l){ s[0] = l; return 1; }
    s[0] = row; s[1] = 2*l - row; return 2;
}

// ============== ONE fused init kernel ==============
// blocks 0..18  : CG tensors
// block  19     : threshold sort (g_T) + slot descriptors
// blocks 20..266: A/B table chunks (local sort recomputed per block -> no dependency)
__global__ void k_init_all(const float* __restrict__ W1, const float* __restrict__ b1,
                           const float* __restrict__ W2){
    int bid = blockIdx.x;
    int t = threadIdx.x;

    if (bid < 19){
        int tens = bid;
        int lo = d_TLO[tens], li = d_TLI[tens], lf = d_TLF[tens];
        int da = 2*lo+1, db = 2*li+1, dc = 2*lf+1;
        int n = da*db*dc;
        __shared__ float sre[225], sim2[225];
        __shared__ float sF[12], sFi[12];
        __shared__ float s_pref0, s_inv2j3, s_nr, s_ni;
        if (t == 0){
            float f = 1.f;
            sF[0] = 1.f; sFi[0] = 1.f;
            for (int i = 1; i < 12; i++){ f *= (float)i; sF[i] = f; sFi[i] = 1.f/f; }
            s_pref0 = sqrtf((float)(2*lf+1) * sF[lo+li-lf] * sF[lo-li+lf] * sF[-lo+li+lf] * sFi[lo+li+lf+1]);
            s_inv2j3 = rsqrtf((float)(2*lf+1));
        }
        __syncthreads();
        const float* F = sF; const float* Fi = sFi;
        for (int e = t; e < n; e += blockDim.x){
            int cc = e % dc; int ab = e / dc; int b = ab % db; int a = ab / db;
            int mset[2], nset[2], kset[2];
            int nm = qcols(lo, a, mset);
            int nn = qcols(li, b, nset);
            int nk = qcols(lf, cc, kset);
            float re = 0.f, imv = 0.f;
            for (int i1 = 0; i1 < nm; i1++){
                float q1r, q1i; qvalcf(lo, a, mset[i1], q1r, q1i);
                for (int i2 = 0; i2 < nn; i2++){
                    float q2r, q2i; qvalcf(li, b, nset[i2], q2r, q2i);
                    float q12r = q1r*q2r - q1i*q2i;
                    float q12i = q1r*q2i + q1i*q2r;
                    for (int i3 = 0; i3 < nk; i3++){
                        float q3r, q3i; qvalcf(lf, cc, kset[i3], q3r, q3i);
                        float w = w3j_entryf(lo, li, lf, mset[i1], nset[i2], kset[i3], F, Fi, s_pref0, s_inv2j3);
                        if (w != 0.f){
                            re  += (q12r*q3r - q12i*q3i) * w;
                            imv += (q12r*q3i + q12i*q3r) * w;
                        }
                    }
                }
            }
            sre[e] = re; sim2[e] = imv;
        }
        __syncthreads();
        if (t == 0){
            float nr = 0.f, ni = 0.f;
            for (int e = 0; e < n; e++){ nr += sre[e]*sre[e]; ni += sim2[e]*sim2[e]; }
            s_nr = nr; s_ni = ni;
        }
        __syncthreads();
        bool use_re = (s_nr >= s_ni);
        float inv = rsqrtf(use_re ? s_nr : s_ni);
        int base = d_CGOFF[tens];
        for (int e = t; e < n; e += blockDim.x)
            g_CG[base + e] = (use_re ? sre[e] : sim2[e]) * inv;
        return;
    }

    if (bid == 19){
        __shared__ float th[HID];
        if (t < HID){
            float w = W1[t];
            th[t] = (w != 0.0f) ? (-b1[t] / w) : -1e30f;
        }
        __syncthreads();
        if (t < HID){
            float mine = th[t];
            int rank = 0;
            for (int i = 0; i < HID; i++){
                float o = th[i];
                rank += (o < mine) || (o == mine && i < t);
            }
            g_T[rank] = mine;
        }
        if (t == 0){
            int s = 0;
            for (int pair = 0; pair < 9; pair++){
                int lo = pair/3, li = pair%3;
                int da = 2*lo+1, db = 2*li+1;
                int nlf = d_NLF[pair], kp = d_KP[pair];
                int lfmin = (lo > li) ? lo - li : li - lo;
                for (int a = 0; a < da; a++)
                    for (int k = 0; k < nlf; k++)
                        for (int b = 0; b < db; b++){
                            int lf = lfmin + k;
                            int cgbase = d_CGOFF[d_TBASE[pair]+k] + (a*db + b)*(2*lf+1);
                            int tgt = d_CYTB[pair] + (b*da + a)*kp + k;
                            g_slotdesc[s++] = cgbase | (lf<<11) | (lo<<14) | (li<<16) | (tgt<<18);
                        }
            }
        }
        return;
    }

    // ---- A/B table blocks (local sort recomputed -> no dependency on block 19) ----
    {
        int pb = bid - 20;
        int px = pb % 19, py = pb / 19;
        int s0 = py * ABCHUNK;

        __shared__ float sW1[HID], sb1[HID], sth[HID];
        __shared__ int   ssid[HID], srnk[HID];
        if (t < HID){
            float w = W1[t], bb = b1[t];
            sW1[t] = w; sb1[t] = bb;
            sth[t] = (w != 0.0f) ? (-bb / w) : -1e30f;
        }
        __syncthreads();
        if (t < HID){
            float mine = sth[t];
            int rank = 0;
            for (int i = 0; i < HID; i++){
                float o = sth[i];
                rank += (o < mine) || (o == mine && i < t);
            }
            srnk[t] = rank;
            ssid[rank] = t;
        }
        __syncthreads();

        int p = px*256 + t;             // 19*256 == NPATH exactly
        int pn = permute_pad(p);

        float A = 0.f, Bv = 0.f;
        for (int tt = 0; tt < HID; tt++){
            float w = sW1[tt], bb = sb1[tt];
            int rk = srnk[tt];
            bool act = (w > 0.0f) ? (rk < s0) : ((w < 0.0f) ? (rk >= s0) : (bb > 0.0f));
            if (act){
                float w2 = W2[tt*NPATH + p];
                A  = fmaf(w,  w2, A);
                Bv = fmaf(bb, w2, Bv);
            }
        }
        g_A[s0*NPAD + pn] = A;
        g_B[s0*NPAD + pn] = Bv;
        #pragma unroll
        for (int d = 1; d < ABCHUNK; d++){
            int s = s0 + d;
            if (s >= NSEG) break;
            int u  = ssid[s-1];
            float w = sW1[u], bb = sb1[u];
            float w2 = W2[u*NPATH + p];
            float sg = (w > 0.0f) ? 1.0f : ((w < 0.0f) ? -1.0f : 0.0f);
            A  = fmaf(sg*w,  w2, A);
            Bv = fmaf(sg*bb, w2, Bv);
            g_A[s*NPAD + pn] = A;
            g_B[s*NPAD + pn] = Bv;
        }
    }
}

// ============== main kernel: one CTA per point ==============
template<int DA,int NLF,int KP>
__device__ __forceinline__ void pass(const float* __restrict__ cyb,  // sCYT + CYB + j*DA*KP
                                     const float* __restrict__ cfb,  // sC + PB + v*17*KP
                                     float* __restrict__ outp,       // out + rowbase*144 + col
                                     int u0, int NU){
    float cy[DA*NLF];
    #pragma unroll
    for (int i = 0; i < DA; i++){
        if (KP == 4 && NLF == 3){
            float4 v4 = *(const float4*)(cyb + i*KP);
            cy[i*NLF+0]=v4.x; cy[i*NLF+1]=v4.y; cy[i*NLF+2]=v4.z;
        } else if (KP == 8 && NLF == 5){
            float4 v4 = *(const float4*)(cyb + i*KP);
            cy[i*NLF+0]=v4.x; cy[i*NLF+1]=v4.y; cy[i*NLF+2]=v4.z; cy[i*NLF+3]=v4.w;
            cy[i*NLF+4]=cyb[i*KP+4];
        } else {
            #pragma unroll
            for (int k = 0; k < NLF; k++) cy[i*NLF+k] = cyb[i*KP+k];
        }
    }
    for (int ug = 0; ug < NU; ug++){
        const float* cfp = cfb + (u0+ug)*KP;
        float cf[NLF];
        if (KP == 4 && NLF == 3){
            float4 v4 = *(const float4*)cfp;
            cf[0]=v4.x; cf[1]=v4.y; cf[2]=v4.z;
        } else if (KP == 8 && NLF == 5){
            float4 v4 = *(const float4*)cfp;
            cf[0]=v4.x; cf[1]=v4.y; cf[2]=v4.z; cf[3]=v4.w; cf[4]=cfp[4];
        } else {
            #pragma unroll
            for (int k = 0; k < NLF; k++) cf[k] = cfp[k];
        }
        #pragma unroll
        for (int i = 0; i < DA; i++){
            float val = 0.f;
            #pragma unroll
            for (int k = 0; k < NLF; k++) val = fmaf(cy[i*NLF+k], cf[k], val);
            __stcs(outp + (ug*DA + i)*144, val);
        }
    }
}

template<int DA,int NLF1,int KP1,int NLF2,int KP2>
__device__ __forceinline__ void warp_work(const float* __restrict__ sC,
                                          const float* __restrict__ sCYT,
                                          float* __restrict__ outz,
                                          int l, int u0, int NU, int loBase,
                                          int PB0, int PB1, int PB2,
                                          int CY0, int CY1, int CY2){
    int c16 = l & 15, h = l >> 4;
    int NU0 = (NU + 1) >> 1;
    int u0h = h ? (u0 + NU0) : u0;
    int NUh = h ? (NU - NU0) : NU0;
    float* outw = outz + (loBase + u0 *DA)*144;
    float* outh = outz + (loBase + u0h*DA)*144;

    pass<DA,1,1>(sCYT + CY0, sC + PB0 + c16*17, outh + c16, u0h, NUh);
    { int cc = l; int v = cc/3, j = cc - 3*v;
      pass<DA,NLF1,KP1>(sCYT + CY1 + j*DA*KP1, sC + PB1 + v*17*KP1, outw + 16 + cc, u0, NU); }
    { int cc = 32 + c16; int v = cc/3, j = cc - 3*v;
      pass<DA,NLF1,KP1>(sCYT + CY1 + j*DA*KP1, sC + PB1 + v*17*KP1, outh + 16 + cc, u0h, NUh); }
    { int cc = l; int v = cc/5, j = cc - 5*v;
      pass<DA,NLF2,KP2>(sCYT + CY2 + j*DA*KP2, sC + PB2 + v*17*KP2, outw + 64 + cc, u0, NU); }
    { int cc = 32 + l; int v = cc/5, j = cc - 5*v;
      pass<DA,NLF2,KP2>(sCYT + CY2 + j*DA*KP2, sC + PB2 + v*17*KP2, outw + 64 + cc, u0, NU); }
    { int cc = 64 + c16; int v = cc/5, j = cc - 5*v;
      pass<DA,NLF2,KP2>(sCYT + CY2 + j*DA*KP2, sC + PB2 + v*17*KP2, outh + 64 + cc, u0h, NUh); }
}

extern __shared__ float smem[];

__global__ __launch_bounds__(288, 4)
void k_main(const float* __restrict__ r, float* __restrict__ out){
    float* sC   = smem;             // NPAD = 6800
    float* sCYT = sC + NPAD;        // 376
    float* sY   = sCYT + NCYT;      // 32

    int z   = blockIdx.x;
    int tid = threadIdx.x;
    int w   = tid >> 5, l = tid & 31;

    float x = r[3*z+0], y = r[3*z+1], zz = r[3*z+2];
    float rad = sqrtf(x*x + y*y + zz*zz);
    bool  iszero = (rad == 0.0f);
    float inv = 1.0f / fmaxf(rad, 1e-12f);
    float ux = x*inv, uy = y*inv, uz = zz*inv;

    if (tid == 0){
        float X = ux, Y = uy, Z = uz;
        float X2 = X*X, Y2 = Y*Y, Z2 = Z*Z;
        sY[0]  = 0.28209479177387814f;
        sY[1]  = 0.4886025119029199f * Y;
        sY[2]  = 0.4886025119029199f * Z;
        sY[3]  = 0.4886025119029199f * X;
        sY[4]  = 1.0925484305920792f * X*Y;
        sY[5]  = 1.0925484305920792f * Y*Z;
        sY[6]  = 0.31539156525252005f * (3.f*Z2 - 1.f);
        sY[7]  = 1.0925484305920792f * X*Z;
        sY[8]  = 0.5462742152960396f * (X2 - Y2);
        sY[9]  = 0.5900435899266435f * Y*(3.f*X2 - Y2);
        sY[10] = 2.890611442640554f  * X*Y*Z;
        sY[11] = 0.4570457994644658f * Y*(5.f*Z2 - 1.f);
        sY[12] = 0.3731763325901154f * Z*(5.f*Z2 - 3.f);
        sY[13] = 0.4570457994644658f * X*(5.f*Z2 - 1.f);
        sY[14] = 1.445305721320277f  * (X2 - Y2)*Z;
        sY[15] = 0.5900435899266435f * X*(X2 - 3.f*Y2);
        sY[16] = 2.5033429417967046f * X*Y*(X2 - Y2);
        sY[17] = 1.7701307697799304f * Y*(3.f*X2 - Y2)*Z;
        sY[18] = 0.9461746957575601f * X*Y*(7.f*Z2 - 1.f);
        sY[19] = 0.6690465435572892f * Y*Z*(7.f*Z2 - 3.f);
        sY[20] = 0.10578554691520431f * (35.f*Z2*Z2 - 30.f*Z2 + 3.f);
        sY[21] = 0.6690465435572892f * X*Z*(7.f*Z2 - 3.f);
        sY[22] = 0.47308734787878004f * (X2 - Y2)*(7.f*Z2 - 1.f);
        sY[23] = 1.7701307697799304f * X*(X2 - 3.f*Y2)*Z;
        sY[24] = 0.6258357354491761f * (X2*X2 - 6.f*X2*Y2 + Y2*Y2);
    }
    // zero CY pad region (376 words)
    if (tid < 188){ sCYT[tid] = 0.f; sCYT[tid + 188] = 0.f; }

    bool pred = (tid < HID) && (g_T[tid] < rad);
    int seg = __syncthreads_count(pred);     // barrier: sY + zeros visible

    // coeff fill (padded layout), float4: 6800/4 = 1700
    {
        const float4* A4 = (const float4*)(g_A + (size_t)seg * NPAD);
        const float4* B4 = (const float4*)(g_B + (size_t)seg * NPAD);
        float4* sC4 = (float4*)sC;
        #pragma unroll
        for (int it = 0; it < 6; it++){
            int idx = it*288 + tid;
            if (idx < NPAD/4){
                float4 a = __ldg(&A4[idx]);
                float4 b = __ldg(&B4[idx]);
                sC4[idx] = make_float4(fmaf(rad,a.x,b.x), fmaf(rad,a.y,b.y),
                                       fmaf(rad,a.z,b.z), fmaf(rad,a.w,b.w));
            }
        }
    }

    // CY fill into padded CYT
    if (tid < 259){
        int desc = g_slotdesc[tid];
        int cgbase = desc & 0x7FF;
        int lf  = (desc >> 11) & 7;
        int lo  = (desc >> 14) & 3;
        int li  = (desc >> 16) & 3;
        int tgt = desc >> 18;
        int yoff = lf*lf, dc = 2*lf + 1;
        float v = 0.f;
        for (int m = 0; m < dc; m++)
            v = fmaf(g_CG[cgbase + m], sY[yoff + m], v);
        float lm = sqrtf((float)(2*li+1) * 12.566370614359172f);
        float num = (lo == 0) ? 48.f : ((lo == 1) ? 112.f : 144.f);
        float nrm = iszero ? (lm * 0.25f) : (lm * rsqrtf(num));
        sCYT[tgt] = v * nrm;
    }
    __syncthreads();

    float* outz = out + (size_t)z * 20736;
    if (w == 0){
        warp_work<1,1,1,1,1>(sC, sCYT, outz, l, 0, 16, 0,
                             0, 272, 544, 0, 1, 4);
    } else if (w < 4){
        int u0 = (w == 1) ? 0 : ((w == 2) ? 6 : 11);
        int NU = (w == 1) ? 6 : 5;
        warp_work<3,3,4,3,4>(sC, sCYT, outz, l, u0, NU, 16,
                             816, 1088, 2176, 9, 12, 48);
    } else {
        int wi = w - 4;
        int u0 = (wi == 0) ? 0 : (4 + 3*(wi-1));   // 0,4,7,10,13
        int NU = (wi == 0) ? 4 : 3;
        warp_work<5,3,4,5,8>(sC, sCYT, outz, l, u0, NU, 64,
                             3264, 3536, 4624, 108, 116, 176);
    }
}

extern "C" void kernel_launch(void* const* d_in, const int* in_sizes, int n_in,
                              void* d_out, int out_size){
    const float* r  = (const float*)d_in[0];
    const float* W1 = (const float*)d_in[1];
    const float* b1 = (const float*)d_in[2];
    const float* W2 = (const float*)d_in[3];
    float* out = (float*)d_out;

    static bool attr_set = false;
    int smem_bytes = (NPAD + NCYT + 32) * 4;
    if (!attr_set){
        cudaFuncSetAttribute(k_main, cudaFuncAttributeMaxDynamicSharedMemorySize, smem_bytes);
        attr_set = true;
    }

    k_init_all<<<20 + 19*((NSEG + ABCHUNK - 1)/ABCHUNK), 256>>>(W1, b1, W2);
    k_main<<<NPTS, 288, smem_bytes>>>(r, out);
}

// round 17
// speedup vs baseline: 1.1323x; 1.0122x over previous
#include <cuda_runtime.h>
#include <cuda_fp16.h>
#include <math.h>
#include <stdint.h>

#define HID     100
#define NPATH   4864
#define NPADH   6400          // half2 AB table: per pair (u*16+v)*KP+k
#define NSEG    101
#define NCYT    376           // k-padded CY table
#define ABCHUNK 8
#define NPTS    8192

// ---------------- static device scratch (zero-initialized -> pads stay 0) ----------------
__device__ float g_T[HID];
__device__ float g_CG[1225];
__device__ int   g_slotdesc[259];
__device__ __align__(16) __half2 g_AB[NSEG*NPADH];   // (A,B) packed fp16

__constant__ int d_NLF[9]   = {1,1,1, 1,3,3, 1,3,5};
__constant__ int d_KP[9]    = {1,1,1, 1,4,4, 1,4,8};
__constant__ int d_TBASE[9] = {0,1,2, 3,4,7, 10,11,14};
__constant__ int d_CYTB[9]  = {0,1,4, 9,12,48, 108,116,176};
__constant__ int d_CGOFF[19]= {0,1,10,35,44,53,80,125,170,245,350,375,420,495,600,625,700,825,1000};
__constant__ int d_TLO[19]  = {0,0,0,1,1,1,1,1,1,1,2,2,2,2,2,2,2,2,2};
__constant__ int d_TLI[19]  = {0,1,2,0,1,1,1,2,2,2,0,1,1,1,2,2,2,2,2};
__constant__ int d_TLF[19]  = {0,1,2,1,0,1,2,1,2,3,2,1,2,3,0,1,2,3,4};

// original path index -> AB-table index: pairbase + (u*16+v)*KP + k
__device__ __forceinline__ int permute_pad_h(int p){
    int base, nlf, kp, bn;
    if      (p < 256)  { base=0;    nlf=1; kp=1; bn=0;    }
    else if (p < 512)  { base=256;  nlf=1; kp=1; bn=256;  }
    else if (p < 768)  { base=512;  nlf=1; kp=1; bn=512;  }
    else if (p < 1024) { base=768;  nlf=1; kp=1; bn=768;  }
    else if (p < 1792) { base=1024; nlf=3; kp=4; bn=1024; }
    else if (p < 2560) { base=1792; nlf=3; kp=4; bn=2048; }
    else if (p < 2816) { base=2560; nlf=1; kp=1; bn=3072; }
    else if (p < 3584) { base=2816; nlf=3; kp=4; bn=3328; }
    else               { base=3584; nlf=5; kp=8; bn=4352; }
    int local = p - base;
    int u   = local / (16*nlf);
    int rem = local - u*16*nlf;
    int v = rem / nlf, k = rem - v*nlf;
    return bn + (u*16 + v)*kp + k;
}

// ---------------- CG helpers (fp32, reciprocal factorial table) ----------------
__device__ float cgvalf(int j1,int j2,int j3,int m1,int m2,
                        const float* __restrict__ F, const float* __restrict__ Fi,
                        float pref0){
    int m3 = m1 + m2;
    if (abs(m3) > j3) return 0.f;
    float pref = pref0 * sqrtf(F[j3+m3]*F[j3-m3]*F[j1-m1]*F[j1+m1]*F[j2-m2]*F[j2+m2]);
    int klo = max(0, max(j2-j3-m1, j1+m2-j3));
    int khi = min(j1+j2-j3, min(j1-m1, j2+m2));
    float s = 0.f;
    for (int k = klo; k <= khi; k++){
        float d = Fi[k]*Fi[j1+j2-j3-k]*Fi[j1-m1-k]*Fi[j2+m2-k]*Fi[j3-j2+m1+k]*Fi[j3-j1-m2+k];
        s += (k & 1) ? -d : d;
    }
    return pref * s;
}
__device__ __forceinline__ float w3j_entryf(int j1,int j2,int j3,int mi,int ni,int ki,
                                            const float* __restrict__ F, const float* __restrict__ Fi,
                                            float pref0, float inv2j3){
    int m1 = mi - j1, m2 = ni - j2, m3 = ki - j3;
    if (m1 + m2 + m3 != 0) return 0.f;
    float cg = cgvalf(j1, j2, j3, m1, m2, F, Fi, pref0);
    float sgn = ((j1 - j2 + m3) & 1) ? -1.f : 1.f;
    return sgn * cg * inv2j3;
}
__device__ __forceinline__ void qvalcf(int l, int i, int j, float& re, float& im){
    re = 0.f; im = 0.f;
    const float s2 = 0.70710678118654752f;
    int m = i - l;
    if (m == 0){ if (j == l) re = 1.f; return; }
    if (m > 0){
        if (j == l+m)      re = (m & 1) ? -s2 : s2;
        else if (j == l-m) re = s2;
    } else {
        int mm = -m;
        if (j == l-mm)      im = s2;
        else if (j == l+mm) im = (mm & 1) ? s2 : -s2;
    }
}
__device__ __forceinline__ int qcols(int l, int row, int* s){
    if (row == l){ s[0] = l; return 1; }
    s[0] = row; s[1] = 2*l - row; return 2;
}

// ============== ONE fused init kernel ==============
__global__ void k_init_all(const float* __restrict__ W1, const float* __restrict__ b1,
                           const float* __restrict__ W2){
    int bid = blockIdx.x;
    int t = threadIdx.x;

    if (bid < 19){
        int tens = bid;
        int lo = d_TLO[tens], li = d_TLI[tens], lf = d_TLF[tens];
        int da = 2*lo+1, db = 2*li+1, dc = 2*lf+1;
        int n = da*db*dc;
        __shared__ float sre[225], sim2[225];
        __shared__ float sF[12], sFi[12];
        __shared__ float s_pref0, s_inv2j3, s_nr, s_ni;
        if (t == 0){
            float f = 1.f;
            sF[0] = 1.f; sFi[0] = 1.f;
            for (int i = 1; i < 12; i++){ f *= (float)i; sF[i] = f; sFi[i] = 1.f/f; }
            s_pref0 = sqrtf((float)(2*lf+1) * sF[lo+li-lf] * sF[lo-li+lf] * sF[-lo+li+lf] * sFi[lo+li+lf+1]);
            s_inv2j3 = rsqrtf((float)(2*lf+1));
        }
        __syncthreads();
        const float* F = sF; const float* Fi = sFi;
        for (int e = t; e < n; e += blockDim.x){
            int cc = e % dc; int ab = e / dc; int b = ab % db; int a = ab / db;
            int mset[2], nset[2], kset[2];
            int nm = qcols(lo, a, mset);
            int nn = qcols(li, b, nset);
            int nk = qcols(lf, cc, kset);
            float re = 0.f, imv = 0.f;
            for (int i1 = 0; i1 < nm; i1++){
                float q1r, q1i; qvalcf(lo, a, mset[i1], q1r, q1i);
                for (int i2 = 0; i2 < nn; i2++){
                    float q2r, q2i; qvalcf(li, b, nset[i2], q2r, q2i);
                    float q12r = q1r*q2r - q1i*q2i;
                    float q12i = q1r*q2i + q1i*q2r;
                    for (int i3 = 0; i3 < nk; i3++){
                        float q3r, q3i; qvalcf(lf, cc, kset[i3], q3r, q3i);
                        float w = w3j_entryf(lo, li, lf, mset[i1], nset[i2], kset[i3], F, Fi, s_pref0, s_inv2j3);
                        if (w != 0.f){
                            re  += (q12r*q3r - q12i*q3i) * w;
                            imv += (q12r*q3i + q12i*q3r) * w;
                        }
                    }
                }
            }
            sre[e] = re; sim2[e] = imv;
        }
        __syncthreads();
        if (t == 0){
            float nr = 0.f, ni = 0.f;
            for (int e = 0; e < n; e++){ nr += sre[e]*sre[e]; ni += sim2[e]*sim2[e]; }
            s_nr = nr; s_ni = ni;
        }
        __syncthreads();
        bool use_re = (s_nr >= s_ni);
        float inv = rsqrtf(use_re ? s_nr : s_ni);
        int base = d_CGOFF[tens];
        for (int e = t; e < n; e += blockDim.x)
            g_CG[base + e] = (use_re ? sre[e] : sim2[e]) * inv;
        return;
    }

    if (bid == 19){
        __shared__ float th[HID];
        if (t < HID){
            float w = W1[t];
            th[t] = (w != 0.0f) ? (-b1[t] / w) : -1e30f;
        }
        __syncthreads();
        if (t < HID){
            float mine = th[t];
            int rank = 0;
            for (int i = 0; i < HID; i++){
                float o = th[i];
                rank += (o < mine) || (o == mine && i < t);
            }
            g_T[rank] = mine;
        }
        if (t == 0){
            int s = 0;
            for (int pair = 0; pair < 9; pair++){
                int lo = pair/3, li = pair%3;
                int da = 2*lo+1, db = 2*li+1;
                int nlf = d_NLF[pair], kp = d_KP[pair];
                int lfmin = (lo > li) ? lo - li : li - lo;
                for (int a = 0; a < da; a++)
                    for (int k = 0; k < nlf; k++)
                        for (int b = 0; b < db; b++){
                            int lf = lfmin + k;
                            int cgbase = d_CGOFF[d_TBASE[pair]+k] + (a*db + b)*(2*lf+1);
                            int tgt = d_CYTB[pair] + (b*da + a)*kp + k;
                            g_slotdesc[s++] = cgbase | (lf<<11) | (lo<<14) | (li<<16) | (tgt<<18);
                        }
            }
        }
        return;
    }

    // ---- AB table blocks (local sort recomputed -> no dependency on block 19) ----
    {
        int pb = bid - 20;
        int px = pb % 19, py = pb / 19;
        int s0 = py * ABCHUNK;

        __shared__ float sW1[HID], sb1[HID], sth[HID];
        __shared__ int   ssid[HID], srnk[HID];
        if (t < HID){
            float w = W1[t], bb = b1[t];
            sW1[t] = w; sb1[t] = bb;
            sth[t] = (w != 0.0f) ? (-bb / w) : -1e30f;
        }
        __syncthreads();
        if (t < HID){
            float mine = sth[t];
            int rank = 0;
            for (int i = 0; i < HID; i++){
                float o = sth[i];
                rank += (o < mine) || (o == mine && i < t);
            }
            srnk[t] = rank;
            ssid[rank] = t;
        }
        __syncthreads();

        int p = px*256 + t;             // 19*256 == NPATH exactly
        int pn = permute_pad_h(p);

        float A = 0.f, Bv = 0.f;
        for (int tt = 0; tt < HID; tt++){
            float w = sW1[tt], bb = sb1[tt];
            int rk = srnk[tt];
            bool act = (w > 0.0f) ? (rk < s0) : ((w < 0.0f) ? (rk >= s0) : (bb > 0.0f));
            if (act){
                float w2 = W2[tt*NPATH + p];
                A  = fmaf(w,  w2, A);
                Bv = fmaf(bb, w2, Bv);
            }
        }
        g_AB[s0*NPADH + pn] = __floats2half2_rn(A, Bv);
        #pragma unroll
        for (int d = 1; d < ABCHUNK; d++){
            int s = s0 + d;
            if (s >= NSEG) break;
            int u  = ssid[s-1];
            float w = sW1[u], bb = sb1[u];
            float w2 = W2[u*NPATH + p];
            float sg = (w > 0.0f) ? 1.0f : ((w < 0.0f) ? -1.0f : 0.0f);
            A  = fmaf(sg*w,  w2, A);
            Bv = fmaf(sg*bb, w2, Bv);
            g_AB[s*NPADH + pn] = __floats2half2_rn(A, Bv);
        }
    }
}

// ============== main kernel: one CTA per point, direct-LDG fp16 AB ==============
__device__ __forceinline__ float ab2cf(__half2 h, float rad){
    float2 f = __half22float2(h);
    return fmaf(rad, f.x, f.y);
}

template<int DA,int NLF,int KP>
__device__ __forceinline__ void pass(const float* __restrict__ cyb,    // sCYT + CYB + j*DA*KP
                                     const __half2* __restrict__ abv,  // g_AB + segbase + PB + v*KP
                                     float* __restrict__ outp,         // out + rowbase*144 + col
                                     int u0, int NU, float rad){
    float cy[DA*NLF];
    #pragma unroll
    for (int i = 0; i < DA; i++){
        if (KP == 4 && NLF == 3){
            float4 v4 = *(const float4*)(cyb + i*KP);
            cy[i*NLF+0]=v4.x; cy[i*NLF+1]=v4.y; cy[i*NLF+2]=v4.z;
        } else if (KP == 8 && NLF == 5){
            float4 v4 = *(const float4*)(cyb + i*KP);
            cy[i*NLF+0]=v4.x; cy[i*NLF+1]=v4.y; cy[i*NLF+2]=v4.z; cy[i*NLF+3]=v4.w;
            cy[i*NLF+4]=cyb[i*KP+4];
        } else {
            #pragma unroll
            for (int k = 0; k < NLF; k++) cy[i*NLF+k] = cyb[i*KP+k];
        }
    }
    const __half2* ap = abv + u0*(16*KP);
    for (int ug = 0; ug < NU; ug++){
        float cf[NLF];
        if (KP == 4 && NLF == 3){
            uint4 raw = *(const uint4*)ap;
            cf[0] = ab2cf(*(const __half2*)&raw.x, rad);
            cf[1] = ab2cf(*(const __half2*)&raw.y, rad);
            cf[2] = ab2cf(*(const __half2*)&raw.z, rad);
        } else if (KP == 8 && NLF == 5){
            uint4 raw = *(const uint4*)ap;
            cf[0] = ab2cf(*(const __half2*)&raw.x, rad);
            cf[1] = ab2cf(*(const __half2*)&raw.y, rad);
            cf[2] = ab2cf(*(const __half2*)&raw.z, rad);
            cf[3] = ab2cf(*(const __half2*)&raw.w, rad);
            cf[4] = ab2cf(ap[4], rad);
        } else {
            #pragma unroll
            for (int k = 0; k < NLF; k++) cf[k] = ab2cf(ap[k], rad);
        }
        ap += 16*KP;
        #pragma unroll
        for (int i = 0; i < DA; i++){
            float val = 0.f;
            #pragma unroll
            for (int k = 0; k < NLF; k++) val = fmaf(cy[i*NLF+k], cf[k], val);
            __stcs(outp + (ug*DA + i)*144, val);
        }
    }
}

template<int DA,int NLF1,int KP1,int NLF2,int KP2>
__device__ __forceinline__ void warp_work(const __half2* __restrict__ abz,
                                          const float* __restrict__ sCYT,
                                          float* __restrict__ outz,
                                          int l, int u0, int NU, int loBase, float rad,
                                          int PB0, int PB1, int PB2,
                                          int CY0, int CY1, int CY2){
    int c16 = l & 15, h = l >> 4;
    int NU0 = (NU + 1) >> 1;
    int u0h = h ? (u0 + NU0) : u0;
    int NUh = h ? (NU - NU0) : NU0;
    float* outw = outz + (loBase + u0 *DA)*144;
    float* outh = outz + (loBase + u0h*DA)*144;

    pass<DA,1,1>(sCYT + CY0, abz + PB0 + c16, outh + c16, u0h, NUh, rad);
    { int cc = l; int v = cc/3, j = cc - 3*v;
      pass<DA,NLF1,KP1>(sCYT + CY1 + j*DA*KP1, abz + PB1 + v*KP1, outw + 16 + cc, u0, NU, rad); }
    { int cc = 32 + c16; int v = cc/3, j = cc - 3*v;
      pass<DA,NLF1,KP1>(sCYT + CY1 + j*DA*KP1, abz + PB1 + v*KP1, outh + 16 + cc, u0h, NUh, rad); }
    { int cc = l; int v = cc/5, j = cc - 5*v;
      pass<DA,NLF2,KP2>(sCYT + CY2 + j*DA*KP2, abz + PB2 + v*KP2, outw + 64 + cc, u0, NU, rad); }
    { int cc = 32 + l; int v = cc/5, j = cc - 5*v;
      pass<DA,NLF2,KP2>(sCYT + CY2 + j*DA*KP2, abz + PB2 + v*KP2, outw + 64 + cc, u0, NU, rad); }
    { int cc = 64 + c16; int v = cc/5, j = cc - 5*v;
      pass<DA,NLF2,KP2>(sCYT + CY2 + j*DA*KP2, abz + PB2 + v*KP2, outh + 64 + cc, u0h, NUh, rad); }
}

extern __shared__ float smem[];

__global__ __launch_bounds__(288, 4)
void k_main(const float* __restrict__ r, float* __restrict__ out){
    float* sCYT = smem;             // 376
    float* sY   = sCYT + NCYT;      // 32

    int z   = blockIdx.x;
    int tid = threadIdx.x;
    int w   = tid >> 5, l = tid & 31;

    float x = r[3*z+0], y = r[3*z+1], zz = r[3*z+2];
    float rad = sqrtf(x*x + y*y + zz*zz);
    bool  iszero = (rad == 0.0f);
    float inv = 1.0f / fmaxf(rad, 1e-12f);
    float ux = x*inv, uy = y*inv, uz = zz*inv;

    if (tid == 0){
        float X = ux, Y = uy, Z = uz;
        float X2 = X*X, Y2 = Y*Y, Z2 = Z*Z;
        sY[0]  = 0.28209479177387814f;
        sY[1]  = 0.4886025119029199f * Y;
        sY[2]  = 0.4886025119029199f * Z;
        sY[3]  = 0.4886025119029199f * X;
        sY[4]  = 1.0925484305920792f * X*Y;
        sY[5]  = 1.0925484305920792f * Y*Z;
        sY[6]  = 0.31539156525252005f * (3.f*Z2 - 1.f);
        sY[7]  = 1.0925484305920792f * X*Z;
        sY[8]  = 0.5462742152960396f * (X2 - Y2);
        sY[9]  = 0.5900435899266435f * Y*(3.f*X2 - Y2);
        sY[10] = 2.890611442640554f  * X*Y*Z;
        sY[11] = 0.4570457994644658f * Y*(5.f*Z2 - 1.f);
        sY[12] = 0.3731763325901154f * Z*(5.f*Z2 - 3.f);
        sY[13] = 0.4570457994644658f * X*(5.f*Z2 - 1.f);
        sY[14] = 1.445305721320277f  * (X2 - Y2)*Z;
        sY[15] = 0.5900435899266435f * X*(X2 - 3.f*Y2);
        sY[16] = 2.5033429417967046f * X*Y*(X2 - Y2);
        sY[17] = 1.7701307697799304f * Y*(3.f*X2 - Y2)*Z;
        sY[18] = 0.9461746957575601f * X*Y*(7.f*Z2 - 1.f);
        sY[19] = 0.6690465435572892f * Y*Z*(7.f*Z2 - 3.f);
        sY[20] = 0.10578554691520431f * (35.f*Z2*Z2 - 30.f*Z2 + 3.f);
        sY[21] = 0.6690465435572892f * X*Z*(7.f*Z2 - 3.f);
        sY[22] = 0.47308734787878004f * (X2 - Y2)*(7.f*Z2 - 1.f);
        sY[23] = 1.7701307697799304f * X*(X2 - 3.f*Y2)*Z;
        sY[24] = 0.6258357354491761f * (X2*X2 - 6.f*X2*Y2 + Y2*Y2);
    }
    // zero CY pad region (376 words)
    if (tid < 188){ sCYT[tid] = 0.f; sCYT[tid + 188] = 0.f; }

    bool pred = (tid < HID) && (g_T[tid] < rad);
    int seg = __syncthreads_count(pred);     // barrier: sY + zeros visible

    // CY fill into padded CYT
    if (tid < 259){
        int desc = g_slotdesc[tid];
        int cgbase = desc & 0x7FF;
        int lf  = (desc >> 11) & 7;
        int lo  = (desc >> 14) & 3;
        int li  = (desc >> 16) & 3;
        int tgt = desc >> 18;
        int yoff = lf*lf, dc = 2*lf + 1;
        float v = 0.f;
        for (int m = 0; m < dc; m++)
            v = fmaf(g_CG[cgbase + m], sY[yoff + m], v);
        float lm = sqrtf((float)(2*li+1) * 12.566370614359172f);
        float num = (lo == 0) ? 48.f : ((lo == 1) ? 112.f : 144.f);
        float nrm = iszero ? (lm * 0.25f) : (lm * rsqrtf(num));
        sCYT[tgt] = v * nrm;
    }
    __syncthreads();

    const __half2* abz = g_AB + (size_t)seg * NPADH;
    float* outz = out + (size_t)z * 20736;
    if (w == 0){
        warp_work<1,1,1,1,1>(abz, sCYT, outz, l, 0, 16, 0, rad,
                             0, 256, 512, 0, 1, 4);
    } else if (w < 4){
        int u0 = (w == 1) ? 0 : ((w == 2) ? 6 : 11);
        int NU = (w == 1) ? 6 : 5;
        warp_work<3,3,4,3,4>(abz, sCYT, outz, l, u0, NU, 16, rad,
                             768, 1024, 2048, 9, 12, 48);
    } else {
        int wi = w - 4;
        int u0 = (wi == 0) ? 0 : (4 + 3*(wi-1));   // 0,4,7,10,13
        int NU = (wi == 0) ? 4 : 3;
        warp_work<5,3,4,5,8>(abz, sCYT, outz, l, u0, NU, 64, rad,
                             3072, 3328, 4352, 108, 116, 176);
    }
}

extern "C" void kernel_launch(void* const* d_in, const int* in_sizes, int n_in,
                              void* d_out, int out_size){
    const float* r  = (const float*)d_in[0];
    const float* W1 = (const float*)d_in[1];
    const float* b1 = (const float*)d_in[2];
    const float* W2 = (const float*)d_in[3];
    float* out = (float*)d_out;

    int smem_bytes = (NCYT + 32) * 4;

    k_init_all<<<20 + 19*((NSEG + ABCHUNK - 1)/ABCHUNK), 256>>>(W1, b1, W2);
    k_main<<<NPTS, 288, smem_bytes>>>(r, out);
}